// round 16
// baseline (speedup 1.0000x reference)
#include <cuda_runtime.h>
#include <cuda_bf16.h>
#include <cstdint>

// Flatten 2x2 blocks:
//   out[bc, i*1024 + 4j + 2r + s] = x[bc, 2i+r, 2j+s]
// x: (32, 3, 512, 512) fp32. bc in [0,96), i in [0,256), j in [0,256).
//
// FINAL — confirmed optimum over a 15-round search. The task is pinned at
// the sustained mixed-R/W DRAM floor: 201 MB compulsory traffic per graph
// replay (bijective permutation of random data; working set 201 MB >
// 126 MB L2; evict_last/evict_first policy hints inert without the
// persisting-L2 carveout, which the harness forbids).
//
// Confirmed levers:
//  - geometry: 3072 CTAs x 1024 threads, each CTA one contiguous 32 KB
//    in / 32 KB out strip. Samples 33.28/34.53 here vs >=35.3 for
//    256/512-thread blocks, fatter strips, or persistent grids.
//  - Blackwell 256-bit stores (st.global.v8.f32): best bench mean and
//    best profiled HBM (5541-5616 GB/s, DRAM 70-71%).
// Dead ends (bench-neutral or worse): MLP scaling, L2 residency policies
// (both polarities), DRAM burst reordering, persistent single-wave grid,
// 256-bit loads + lane shuffles.
//
// Per thread: 2 coalesced LDG.128 (rows 2i, 2i+1) + 1 STG.256 covering
// two consecutive output float4s:
//   out f4 (i, 2j0)   = {a.x, a.y, b.x, b.y}
//   out f4 (i, 2j0+1) = {a.z, a.w, b.z, b.w}

__global__ __launch_bounds__(1024)
void flatten2x2_kernel(const float4* __restrict__ x4, float4* __restrict__ out4) {
    unsigned tid = threadIdx.x;                 // 0..1023
    unsigned j0  = tid & 127u;                  // j-pair index: j = 2*j0, 2*j0+1
    unsigned di  = tid >> 7;                    // 0..7: i slot within strip
    unsigned blk = blockIdx.x;                  // 0..3071
    unsigned i   = (blk & 31u) * 8u + di;       // i in [0,256)
    unsigned bc  = blk >> 5;                    // 0..95

    // input as float4: row stride 128, image stride 512*128 = 65536
    const float4* base = x4 + (size_t)bc * 65536u + (size_t)(2u * i) * 128u + j0;
    float4 a = __ldg(base);          // row 2i,   cols 4j0..4j0+3
    float4 b = __ldg(base + 128u);   // row 2i+1, cols 4j0..4j0+3

    // output: float4 units, i stride 256, image stride 65536
    float4* op = out4 + (size_t)bc * 65536u + (size_t)i * 256u + 2u * j0;
    asm volatile(
        "st.global.v8.f32 [%0], {%1,%2,%3,%4,%5,%6,%7,%8};"
        :: "l"(op),
           "f"(a.x), "f"(a.y), "f"(b.x), "f"(b.y),
           "f"(a.z), "f"(a.w), "f"(b.z), "f"(b.w)
        : "memory");
}

extern "C" void kernel_launch(void* const* d_in, const int* in_sizes, int n_in,
                              void* d_out, int out_size) {
    const float4* x4 = (const float4*)d_in[0];
    float4* out4 = (float4*)d_out;

    // 96 images x 32 strips (8 i-values each) = 3072 CTAs, 1024 threads
    flatten2x2_kernel<<<3072, 1024>>>(x4, out4);
}